// round 4
// baseline (speedup 1.0000x reference)
#include <cuda_runtime.h>
#include <cstdint>

namespace {

constexpr int CIN  = 64;
constexpr int H    = 56;
constexpr int W    = 56;
constexpr int OC   = 64;
constexpr int TH   = 4;            // output rows per block
constexpr int NR   = TH + 2;       // x rows staged (halo)
constexpr int NTHR = 512;

constexpr int XS_ELEMS   = NR * CIN * W;        // 21504 floats
constexpr int WS_ELEMS   = 32 * 3 * 3 * OC;     // 18432 floats
constexpr int SMEM_BYTES = (XS_ELEMS + WS_ELEMS) * 4;  // 159744 B

__device__ __forceinline__ uint64_t bcast_f32x2(float s) {
    uint64_t r;
    asm("mov.b64 %0, {%1, %1};" : "=l"(r) : "f"(s));
    return r;
}
__device__ __forceinline__ void fma_f32x2(uint64_t& d, uint64_t a, uint64_t b) {
    asm("fma.rn.f32x2 %0, %1, %2, %0;" : "+l"(d) : "l"(a), "l"(b));
}

// y[b,i,h,w] = sum_{l,j,k} w[l,j,k,i] * s(b,l,k,h+j-1,w)
// s(b,l,k,h',w) = A(l,h',w+k-1) + A(l+32,((w-1)%W)+k-1)
// A(c,h',u) = (0<=u<W) ? x[b,c,h',(u-1+W)%W] : 0 ; h' out of [0,H) -> 0
__global__ __launch_bounds__(NTHR, 1)
void shift_conv_kernel(const float* __restrict__ x,
                       const float* __restrict__ wt,
                       float* __restrict__ y)
{
    extern __shared__ float smem[];
    float* xs = smem;               // [NR][CIN][W]
    float* ws = smem + XS_ELEMS;    // [288][OC], same linear layout as wt

    const int b   = blockIdx.y;
    const int h0  = blockIdx.x * TH;
    const int tid = threadIdx.x;

    // Stage all weights (layout matches global exactly)
    for (int idx = tid; idx < WS_ELEMS; idx += NTHR) ws[idx] = wt[idx];

    // Stage 6 x rows (zero-filled outside [0,H)) as float4
    const float* xb = x + (size_t)b * CIN * H * W;
    for (int idx = tid; idx < NR * CIN * (W / 4); idx += NTHR) {
        int f4 = idx % (W / 4);
        int rc = idx / (W / 4);
        int c  = rc % CIN;
        int rr = rc / CIN;
        int hp = h0 - 1 + rr;
        float4 v = make_float4(0.f, 0.f, 0.f, 0.f);
        if (0 <= hp && hp < H)
            v = *reinterpret_cast<const float4*>(xb + ((size_t)c * H + hp) * W + f4 * 4);
        *reinterpret_cast<float4*>(xs + (rr * CIN + c) * W + f4 * 4) = v;
    }
    __syncthreads();

    // Thread tiling: hh in [0,4) x-row, ig in [0,8) 8-outch group, wg in [0,14) 4-wide w group
    const int hh = tid >> 7;
    const int r  = tid & 127;
    const int ig = r >> 4;
    const int wg = r & 15;
    if (wg >= 14) return;           // no further __syncthreads below

    const int  i0     = ig * 8;
    const int  w0     = wg * 4;
    const int  h      = h0 + hh;
    const bool w0zero = (w0 == 0);

    // Column parameter m = w + k - 2 spans [w0-2, w0+3] (6 columns).
    //  A-half: valid iff -1 <= m <= W-2, fetch (m+W)%W
    //  B-half (w>=1): valid iff m >= 0,  fetch (m-1+W)%W   (m <= W-1 always)
    int aidx[6], bidx[6];
    unsigned amask = 0, bmask = 0;
    #pragma unroll
    for (int t = 0; t < 6; ++t) {
        int m = w0 - 2 + t;
        int ma = m;                      // (m+W)%W for m in [-2, W+1]
        if (ma < 0)  ma += W;
        if (ma >= W) ma -= W;
        int mb = m - 1;                  // (m-1+W)%W
        if (mb < 0)  mb += W;
        if (mb >= W) mb -= W;
        aidx[t] = ma;
        bidx[t] = mb;
        if (m >= -1 && m <= W - 2) amask |= 1u << t;
        if (m >= 0)                bmask |= 1u << t;
    }
    // w == 0 special B taps (only the w0==0 tile, t=0..2): {x[W-3], x[W-2], 0}
    const int  b0idx0 = w0zero ? (W - 3) : bidx[0];
    const int  b0idx1 = w0zero ? (W - 2) : bidx[1];
    const int  b0idx2 = bidx[2];
    const bool b0v0   = w0zero ? true  : (((bmask >> 0) & 1u) != 0u);
    const bool b0v1   = w0zero ? true  : (((bmask >> 1) & 1u) != 0u);
    const bool b0v2   = w0zero ? false : (((bmask >> 2) & 1u) != 0u);

    // acc2[p][q]: packed pair (outch i0+2p -> lo lane, i0+2p+1 -> hi lane), width w0+q
    uint64_t acc2[4][4];
    #pragma unroll
    for (int p = 0; p < 4; ++p)
        #pragma unroll
        for (int q = 0; q < 4; ++q) acc2[p][q] = 0ull;

    for (int l = 0; l < 32; ++l) {
        #pragma unroll
        for (int j = 0; j < 3; ++j) {
            const float* xA = xs + ((hh + j) * CIN + l) * W;
            const float* xB = xs + ((hh + j) * CIN + l + 32) * W;

            float va[6], vb[6], v0[3];
            #pragma unroll
            for (int t = 0; t < 6; ++t) {
                va[t] = ((amask >> t) & 1u) ? xA[aidx[t]] : 0.f;
                vb[t] = ((bmask >> t) & 1u) ? xB[bidx[t]] : 0.f;
            }
            v0[0] = b0v0 ? xB[b0idx0] : 0.f;
            v0[1] = b0v1 ? xB[b0idx1] : 0.f;
            v0[2] = b0v2 ? xB[b0idx2] : 0.f;

            const float* wrow = ws + ((l * 3 + j) * 3) * OC + i0;
            #pragma unroll
            for (int k = 0; k < 3; ++k) {
                // weight pairs: contiguous outch pairs load straight into f32x2 lanes
                ulonglong2 wp01 = *reinterpret_cast<const ulonglong2*>(wrow + k * OC);
                ulonglong2 wp23 = *reinterpret_cast<const ulonglong2*>(wrow + k * OC + 4);
                const uint64_t wp[4] = {wp01.x, wp01.y, wp23.x, wp23.y};

                float s0 = va[k]     + v0[k];
                float s1 = va[k + 1] + vb[k + 1];
                float s2 = va[k + 2] + vb[k + 2];
                float s3 = va[k + 3] + vb[k + 3];
                const uint64_t sq[4] = {bcast_f32x2(s0), bcast_f32x2(s1),
                                        bcast_f32x2(s2), bcast_f32x2(s3)};
                #pragma unroll
                for (int p = 0; p < 4; ++p) {
                    fma_f32x2(acc2[p][0], wp[p], sq[0]);
                    fma_f32x2(acc2[p][1], wp[p], sq[1]);
                    fma_f32x2(acc2[p][2], wp[p], sq[2]);
                    fma_f32x2(acc2[p][3], wp[p], sq[3]);
                }
            }
        }
    }

    // Unpack: lo lane -> outch i0+2p, hi lane -> outch i0+2p+1
    float* yb = y + (((size_t)b * OC + i0) * H + h) * W + w0;
    #pragma unroll
    for (int p = 0; p < 4; ++p) {
        float4 vlo, vhi;
        float* plo = &vlo.x;
        float* phi = &vhi.x;
        #pragma unroll
        for (int q = 0; q < 4; ++q) {
            plo[q] = __uint_as_float((unsigned)(acc2[p][q] & 0xffffffffu));
            phi[q] = __uint_as_float((unsigned)(acc2[p][q] >> 32));
        }
        *reinterpret_cast<float4*>(yb + (size_t)(2 * p)     * H * W) = vlo;
        *reinterpret_cast<float4*>(yb + (size_t)(2 * p + 1) * H * W) = vhi;
    }
}

} // namespace

extern "C" void kernel_launch(void* const* d_in, const int* in_sizes, int n_in,
                              void* d_out, int out_size)
{
    const float* x  = (const float*)d_in[0];   // [1024,64,56,56] f32
    const float* wt = (const float*)d_in[1];   // [32,3,3,64] f32
    float* y = (float*)d_out;                  // [1024,64,56,56] f32

    cudaFuncSetAttribute(shift_conv_kernel,
                         cudaFuncAttributeMaxDynamicSharedMemorySize, SMEM_BYTES);
    dim3 grid(H / TH, 1024, 1);
    shift_conv_kernel<<<grid, NTHR, SMEM_BYTES>>>(x, wt, y);
}